// round 16
// baseline (speedup 1.0000x reference)
#include <cuda_runtime.h>
#include <math.h>

#define BATCH 256
#define NODE  256
#define DIM   64
#define TOPK  20
#define XLS 68   // padded shared stride for xl rows (16B-aligned for float4)

// ---------------- scratch (device globals; no allocations) ----------------
__device__ int   g_topk[NODE*TOPK];
__device__ float g_agg[65536*DIM];
__device__ float g_p1s[64*256], g_p1q[64*256];     // BN1 partials [c][p]
__device__ float g_p2s[64*512], g_p2q[64*512];     // BN2 partials [c][p]
__device__ float g_mean1[DIM], g_rstd1[DIM];
__device__ float g_mean2[DIM], g_rstd2[DIM];
__device__ float g_W2[16384*7];          // enc_w @ arr_w
__device__ float g_arrP[16*BATCH*7];     // [kc][b][j] partials
__device__ unsigned g_barc[8];           // monotonic ticket barriers

__device__ __forceinline__ float lrelu(float x){ return x >= 0.f ? x : 0.2f*x; }

// device-wide barrier: monotonic counter, 256 arrivals per launch.
// Counter is a multiple of 256 at every launch boundary, so no reset needed.
__device__ __forceinline__ void gsync(int id){
    __syncthreads();
    if (threadIdx.x == 0){
        __threadfence();
        unsigned t = atomicAdd(&g_barc[id], 1u);
        unsigned target = ((t >> 8) + 1u) << 8;
        while (*((volatile unsigned*)&g_barc[id]) < target) { }
        __threadfence();
    }
    __syncthreads();
}

__global__ __launch_bounds__(512,2) void k_all(
        const float* __restrict__ data, const float* __restrict__ lin_w,
        const float* __restrict__ emb,
        const float* __restrict__ att_i, const float* __restrict__ att_j,
        const float* __restrict__ att_em_i, const float* __restrict__ att_em_j,
        const float* __restrict__ bn1_g, const float* __restrict__ bn1_b,
        const float* __restrict__ bn2_g, const float* __restrict__ bn2_b,
        const float* __restrict__ enc_w, const float* __restrict__ enc_b,
        const float* __restrict__ arr_w, const float* __restrict__ arr_b,
        const float* __restrict__ out_w, const float* __restrict__ out_b,
        float* __restrict__ out){
    extern __shared__ float sm[];
    float* xls  = sm;                     // 256*68 = 17408
    float* si   = xls + NODE*XLS;         // 256
    float* sj   = si + NODE;              // 256
    float* attv = sj + NODE;              // 256
    float* U    = attv + 256;             // 10496 floats union

    int b = blockIdx.x;
    int tid = threadIdx.x;

    // ======== stage 0a: W2 rows [b*64, b*64+64) ========
    {
        float* aws = U;                   // 448
        for (int idx=tid; idx<448; idx+=512) aws[idx] = arr_w[idx];
        __syncthreads();
        if (tid < 64){
            int k = b*64 + tid;
            const float4* er = (const float4*)&enc_w[(size_t)k*64];
            float acc[7] = {};
#pragma unroll
            for (int m=0;m<16;m++){
                float4 q = er[m];
                int c = m*4;
#pragma unroll
                for (int j=0;j<7;j++){
                    acc[j] += q.x*aws[(c  )*7+j] + q.y*aws[(c+1)*7+j]
                            + q.z*aws[(c+2)*7+j] + q.w*aws[(c+3)*7+j];
                }
            }
#pragma unroll
            for (int j=0;j<7;j++) g_W2[(size_t)k*7+j] = acc[j];
        }
        __syncthreads();
    }

    // ======== stage 0b: cosine top-k for node i = b (threads 0..255) ========
    {
        float* nrm  = U + 512;            // 256
        float* vals = U + 768;            // 256
        float* wv   = U + 1024;           // 8
        int*   wiS  = (int*)(U + 1032);   // 8
        int*   winp = (int*)(U + 1040);   // 1
        int i = b;
        int lane = tid & 31, warp = tid >> 5;
        if (tid < 256){
            const float* wj = emb + tid*DIM;
            float s = 0.f;
#pragma unroll
            for (int k=0;k<DIM;k++){ float v = wj[k]; s += v*v; }
            nrm[tid] = sqrtf(s);
        }
        __syncthreads();
        if (tid < 256){
            const float* wir = emb + i*DIM;
            const float* wj  = emb + tid*DIM;
            float d = 0.f;
#pragma unroll
            for (int k=0;k<DIM;k++) d += wir[k]*wj[k];
            vals[tid] = d / (nrm[i]*nrm[tid]);
        }
        __syncthreads();
        for (int t=0;t<TOPK;t++){
            if (tid < 256){
                float v = vals[tid]; int idx = tid;
#pragma unroll
                for (int off=16; off; off>>=1){
                    float v2 = __shfl_xor_sync(0xffffffffu, v, off);
                    int   i2 = __shfl_xor_sync(0xffffffffu, idx, off);
                    if (v2 > v || (v2 == v && i2 < idx)){ v = v2; idx = i2; }
                }
                if (lane == 0){ wv[warp] = v; wiS[warp] = idx; }
            }
            __syncthreads();
            if (tid < 8){
                float v8 = wv[tid]; int i8 = wiS[tid];
#pragma unroll
                for (int off=4; off; off>>=1){
                    float v2 = __shfl_xor_sync(0xffu, v8, off);
                    int   i2 = __shfl_xor_sync(0xffu, i8, off);
                    if (v2 > v8 || (v2 == v8 && i2 < i8)){ v8 = v2; i8 = i2; }
                }
                if (tid == 0){ g_topk[i*TOPK + t] = i8; winp[0] = i8; }
            }
            __syncthreads();
            if (tid < 256 && tid == winp[0]) vals[tid] = -3e38f;
            __syncthreads();
        }
    }

    // ======== stage 1 (phase A): xl = data[b] @ lin_w into xls ========
    {
        float* ds = U;             // 64x65
        float* lw = U + 4160;      // 64x65
#pragma unroll
        for (int it=0; it<8; it++){
            int idx = tid + it*512;
            if (idx < 4096) lw[(idx>>6)*65 + (idx&63)] = lin_w[idx];
        }
        if (tid < 64)       attv[tid] = att_i[tid];
        else if (tid < 128) attv[tid] = att_j[tid-64];
        else if (tid < 192) attv[tid] = att_em_i[tid-128];
        else if (tid < 256) attv[tid] = att_em_j[tid-192];

        int tr = tid >> 4;     // 0..31
        int tc = tid & 15;     // 0..15
        const float* datb = data + (size_t)b*NODE*DIM;
        for (int ch=0; ch<4; ch++){
            int r0 = ch*64;
            __syncthreads();
#pragma unroll
            for (int it=0; it<8; it++){
                int idx = tid + it*512;
                ds[(idx>>6)*65 + (idx&63)] = datb[r0*64 + idx];
            }
            __syncthreads();
            float acc[2][4] = {};
#pragma unroll 8
            for (int k=0;k<64;k++){
                float a0 = ds[(tr*2+0)*65 + k];
                float a1 = ds[(tr*2+1)*65 + k];
                float w0 = lw[k*65 + tc*4+0];
                float w1 = lw[k*65 + tc*4+1];
                float w2 = lw[k*65 + tc*4+2];
                float w3 = lw[k*65 + tc*4+3];
                acc[0][0]+=a0*w0; acc[0][1]+=a0*w1; acc[0][2]+=a0*w2; acc[0][3]+=a0*w3;
                acc[1][0]+=a1*w0; acc[1][1]+=a1*w1; acc[1][2]+=a1*w2; acc[1][3]+=a1*w3;
            }
#pragma unroll
            for (int u=0;u<2;u++)
#pragma unroll
                for (int v=0;v<4;v++)
                    xls[(r0+tr*2+u)*XLS + tc*4+v] = acc[u][v];
        }
    }

    gsync(0);   // all g_topk written

    // ======== stage 2 (phases B+C): softmax + aggregation + BN1 partials ========
    {
        int*   tk  = (int*)U;          // 5120 ints
        float* alp = U + 5120;         // 5376 floats
        for (int idx=tid; idx<NODE*TOPK; idx+=512) tk[idx] = g_topk[idx];
        if (tid < 256){
            int i = tid;
            float ai = 0.f, aj = 0.f;
#pragma unroll
            for (int d=0; d<DIM; d++){
                float x = xls[i*XLS + d];
                float e = emb[i*DIM + d];
                ai += x*attv[d]    + e*attv[128+d];
                aj += x*attv[64+d] + e*attv[192+d];
            }
            si[i] = ai; sj[i] = aj;
        }
        __syncthreads();
        if (tid < 256){
            int i = tid;
            float svi = si[i];
            int   sidx[TOPK];
            float lv[TOPK];
#pragma unroll
            for (int k=0;k<TOPK;k++) sidx[k] = tk[i*TOPK+k];
#pragma unroll
            for (int k=0;k<TOPK;k++) lv[k] = lrelu(svi + sj[sidx[k]]);
            float lself = lrelu(svi + sj[i]);
            float m = lself;
#pragma unroll
            for (int k=0;k<TOPK;k++) if (sidx[k] != i) m = fmaxf(m, lv[k]);
            float sum = 0.f;
#pragma unroll
            for (int k=0;k<TOPK;k++){
                float a = (sidx[k] != i) ? expf(lv[k] - m) : 0.f;
                alp[i*21+k] = a; sum += a;
            }
            float as = expf(lself - m);
            alp[i*21+20] = as; sum += as;
            float inv = 1.f/sum;
#pragma unroll
            for (int k=0;k<21;k++) alp[i*21+k] *= inv;
        }
        __syncthreads();

        int w = tid>>5, l = tid&31;
        int half = l>>4;
        int lc = l&15;
        int c0 = 4*lc;
        float sA0=0.f,sA1=0.f,sA2=0.f,sA3=0.f;
        float sQ0=0.f,sQ1=0.f,sQ2=0.f,sQ3=0.f;
#pragma unroll 2
        for (int p=0; p<8; p++){
            int i = w*16 + 2*p + half;
            float ax=0.f, ay=0.f, az=0.f, aw=0.f;
            int base = i*21;
#pragma unroll
            for (int k=0;k<21;k++){
                float a = alp[base+k];
                int s = (k<TOPK) ? tk[i*TOPK+k] : i;
                float4 v = *(const float4*)&xls[s*XLS + c0];
                ax += a*v.x; ay += a*v.y; az += a*v.z; aw += a*v.w;
            }
            int g = b*NODE + i;
            float4 o; o.x=ax; o.y=ay; o.z=az; o.w=aw;
            *(float4*)&g_agg[(size_t)g*DIM + c0] = o;
            sA0+=ax; sQ0+=ax*ax; sA1+=ay; sQ1+=ay*ay;
            sA2+=az; sQ2+=az*az; sA3+=aw; sQ3+=aw*aw;
        }
        sA0 += __shfl_down_sync(0xffffffffu, sA0, 16);
        sA1 += __shfl_down_sync(0xffffffffu, sA1, 16);
        sA2 += __shfl_down_sync(0xffffffffu, sA2, 16);
        sA3 += __shfl_down_sync(0xffffffffu, sA3, 16);
        sQ0 += __shfl_down_sync(0xffffffffu, sQ0, 16);
        sQ1 += __shfl_down_sync(0xffffffffu, sQ1, 16);
        sQ2 += __shfl_down_sync(0xffffffffu, sQ2, 16);
        sQ3 += __shfl_down_sync(0xffffffffu, sQ3, 16);
        __syncthreads();
        float* ssum = U;            // 16*64
        float* ssq  = U + 1024;     // 16*64
        if (l < 16){
            ssum[w*64 + c0  ] = sA0; ssq[w*64 + c0  ] = sQ0;
            ssum[w*64 + c0+1] = sA1; ssq[w*64 + c0+1] = sQ1;
            ssum[w*64 + c0+2] = sA2; ssq[w*64 + c0+2] = sQ2;
            ssum[w*64 + c0+3] = sA3; ssq[w*64 + c0+3] = sQ3;
        }
        __syncthreads();
        if (tid < 64){
            float s=0.f, q=0.f;
#pragma unroll
            for (int ww=0; ww<16; ww++){ s += ssum[ww*64 + tid]; q += ssq[ww*64 + tid]; }
            g_p1s[tid*256 + b] = s;
            g_p1q[tid*256 + b] = q;
        }
    }

    gsync(1);   // all BN1 partials written

    // ======== stage 3: BN1 finalize (blocks 0..63) ========
    if (b < 64){
        float* sh  = U;
        float* shq = U + 256;
        int c = b;
        if (tid < 256){ sh[tid] = g_p1s[c*256 + tid]; shq[tid] = g_p1q[c*256 + tid]; }
        __syncthreads();
#pragma unroll
        for (int off=128; off>32; off>>=1){
            if (tid < off){ sh[tid]+=sh[tid+off]; shq[tid]+=shq[tid+off]; }
            __syncthreads();
        }
        if (tid < 32){
            float a = sh[tid]+sh[tid+32];
            float b2 = shq[tid]+shq[tid+32];
#pragma unroll
            for (int off=16; off; off>>=1){
                a  += __shfl_down_sync(0xffffffffu, a, off);
                b2 += __shfl_down_sync(0xffffffffu, b2, off);
            }
            if (tid == 0){
                double m = (double)a/65536.0;
                double var = (double)b2/65536.0 - m*m;
                g_mean1[c]=(float)m; g_rstd1[c]=1.0f/sqrtf((float)var + 1e-5f);
            }
        }
    }

    gsync(2);   // mean1/rstd1 ready

    // ======== stage 4: encarr — 2 units per block (unit = (kc, batch-group)) ========
    {
        int w = tid>>5, l = tid&31;
        int uhalf = w>>3;                  // 0 or 1
        int wl = w & 7;
        int u = b*2 + uhalf;               // unit id 0..511
        int kc = u >> 5;
        int bxg = u & 31;
        int bb = bxg*8 + wl;
        int kbase = kc*1024;
        int c0 = 4*(l&15);
        int npar = l>>4;

        float4 mn = *(const float4*)&g_mean1[c0];
        float4 rs = *(const float4*)&g_rstd1[c0];
        float4 ga = *(const float4*)&bn1_g[c0];
        float4 be = *(const float4*)&bn1_b[c0];

        const float* arow = g_agg + (size_t)bb*16384 + kbase;
        float acc[7] = {};
        float sA0=0.f,sA1=0.f,sA2=0.f,sA3=0.f;
        float sQ0=0.f,sQ1=0.f,sQ2=0.f,sQ3=0.f;
#pragma unroll
        for (int t=0; t<8; t++){
            int kl = t*128 + l*4;
            float4 v = __ldcs((const float4*)&arow[kl]);
            int n = kc*16 + t*2 + npar;
            float4 e = *(const float4*)&emb[n*64 + c0];
            float gn0 = fmaxf(0.f, (v.x-mn.x)*rs.x*ga.x + be.x);
            float gn1 = fmaxf(0.f, (v.y-mn.y)*rs.y*ga.y + be.y);
            float gn2 = fmaxf(0.f, (v.z-mn.z)*rs.z*ga.z + be.z);
            float gn3 = fmaxf(0.f, (v.w-mn.w)*rs.w*ga.w + be.w);
            float y0 = gn0*e.x, y1 = gn1*e.y, y2 = gn2*e.z, y3 = gn3*e.w;
            sA0+=y0; sQ0+=y0*y0; sA1+=y1; sQ1+=y1*y1;
            sA2+=y2; sQ2+=y2*y2; sA3+=y3; sQ3+=y3*y3;
            const float4* wp = (const float4*)&g_W2[(size_t)(kbase+kl)*7];
            float wf[28];
#pragma unroll
            for (int m=0;m<7;m++){
                float4 q = __ldg(&wp[m]);
                wf[4*m]=q.x; wf[4*m+1]=q.y; wf[4*m+2]=q.z; wf[4*m+3]=q.w;
            }
            float gn[4] = {gn0,gn1,gn2,gn3};
#pragma unroll
            for (int i=0;i<4;i++)
#pragma unroll
                for (int j=0;j<7;j++) acc[j] += gn[i]*wf[i*7+j];
        }
#pragma unroll
        for (int j=0;j<7;j++){
#pragma unroll
            for (int off=16; off; off>>=1)
                acc[j] += __shfl_xor_sync(0xffffffffu, acc[j], off);
        }
        if (l == 0){
#pragma unroll
            for (int j=0;j<7;j++) g_arrP[(kc*256 + bb)*7 + j] = acc[j];
        }
        sA0 += __shfl_down_sync(0xffffffffu, sA0, 16);
        sA1 += __shfl_down_sync(0xffffffffu, sA1, 16);
        sA2 += __shfl_down_sync(0xffffffffu, sA2, 16);
        sA3 += __shfl_down_sync(0xffffffffu, sA3, 16);
        sQ0 += __shfl_down_sync(0xffffffffu, sQ0, 16);
        sQ1 += __shfl_down_sync(0xffffffffu, sQ1, 16);
        sQ2 += __shfl_down_sync(0xffffffffu, sQ2, 16);
        sQ3 += __shfl_down_sync(0xffffffffu, sQ3, 16);
        float* ssum = U + uhalf*1024;        // [8][64]
        float* ssq  = ssum + 512;
        __syncthreads();
        if (l < 16){
            ssum[wl*64 + c0  ] = sA0; ssq[wl*64 + c0  ] = sQ0;
            ssum[wl*64 + c0+1] = sA1; ssq[wl*64 + c0+1] = sQ1;
            ssum[wl*64 + c0+2] = sA2; ssq[wl*64 + c0+2] = sQ2;
            ssum[wl*64 + c0+3] = sA3; ssq[wl*64 + c0+3] = sQ3;
        }
        __syncthreads();
        if (tid < 64){
            float s=0.f, q=0.f;
#pragma unroll
            for (int ww=0; ww<8; ww++){ s += U[ww*64 + tid]; q += U[512 + ww*64 + tid]; }
            int pid = b*2;
            g_p2s[tid*512 + pid] = s;
            g_p2q[tid*512 + pid] = q;
        } else if (tid >= 256 && tid < 320){
            int c = tid - 256;
            float s=0.f, q=0.f;
#pragma unroll
            for (int ww=0; ww<8; ww++){ s += U[1024 + ww*64 + c]; q += U[1536 + ww*64 + c]; }
            int pid = b*2 + 1;
            g_p2s[c*512 + pid] = s;
            g_p2q[c*512 + pid] = q;
        }
    }

    gsync(3);   // all BN2 partials + arrP written

    // ======== stage 5: BN2 finalize (blocks 0..63) + arrfin (blocks 64..70) ========
    if (b < 64){
        float* sh  = U;
        float* shq = U + 256;
        int c = b;
        if (tid < 256){
            sh[tid]  = g_p2s[c*512 + tid] + g_p2s[c*512 + 256 + tid];
            shq[tid] = g_p2q[c*512 + tid] + g_p2q[c*512 + 256 + tid];
        }
        __syncthreads();
#pragma unroll
        for (int off=128; off>32; off>>=1){
            if (tid < off){ sh[tid]+=sh[tid+off]; shq[tid]+=shq[tid+off]; }
            __syncthreads();
        }
        if (tid < 32){
            float a = sh[tid]+sh[tid+32];
            float b2 = shq[tid]+shq[tid+32];
#pragma unroll
            for (int off=16; off; off>>=1){
                a  += __shfl_down_sync(0xffffffffu, a, off);
                b2 += __shfl_down_sync(0xffffffffu, b2, off);
            }
            if (tid == 0){
                double m = (double)a/65536.0;
                double var = (double)b2/65536.0 - m*m;
                g_mean2[c]=(float)m; g_rstd2[c]=1.0f/sqrtf((float)var + 1e-5f);
            }
        }
    } else if (b < 71){
        if (tid < 256){
            int gid = (b-64)*256 + tid;     // < 1792 = 256*7
            int bb = gid / 7, j = gid - bb*7;
            float s = 0.f;
#pragma unroll
            for (int kc=0;kc<16;kc++) s += g_arrP[(kc*256 + bb)*7 + j];
            float bias = arr_b[j];
#pragma unroll
            for (int c=0;c<64;c++) bias += enc_b[c]*arr_w[c*7+j];
            out[65536 + gid] = s + bias;
        }
    }

    gsync(4);   // mean2/rstd2 ready

    // ======== stage 6: score head — 256 rows per block ========
    {
        int w = tid>>5, l = tid&31;
        int d = 2*l;
        for (int r=0; r<16; r++){
            int g = b*256 + r*16 + w;
            int n = g & 255;
            float2 v = __ldcs((const float2*)&g_agg[(size_t)g*DIM + d]);
            float2 e = *(const float2*)&emb[n*DIM + d];
            float gn0 = fmaxf(0.f, (v.x - g_mean1[d  ])*g_rstd1[d  ]*bn1_g[d  ] + bn1_b[d  ]);
            float gn1 = fmaxf(0.f, (v.y - g_mean1[d+1])*g_rstd1[d+1]*bn1_g[d+1] + bn1_b[d+1]);
            float y0 = gn0*e.x, y1 = gn1*e.y;
            float r0 = fmaxf(0.f, (y0 - g_mean2[d  ])*g_rstd2[d  ]*bn2_g[d  ] + bn2_b[d  ]);
            float r1 = fmaxf(0.f, (y1 - g_mean2[d+1])*g_rstd2[d+1]*bn2_g[d+1] + bn2_b[d+1]);
            float p = r0*out_w[d] + r1*out_w[d+1];
#pragma unroll
            for (int off=16; off; off>>=1) p += __shfl_down_sync(0xffffffffu, p, off);
            if (l == 0) out[g] = p + out_b[0];
        }
    }
}

// ---------------- launcher ----------------
extern "C" void kernel_launch(void* const* d_in, const int* in_sizes, int n_in,
                              void* d_out, int out_size){
    const float* data     = (const float*)d_in[0];
    const float* emb      = (const float*)d_in[1];
    const float* lin_w    = (const float*)d_in[2];
    const float* att_i    = (const float*)d_in[3];
    const float* att_j    = (const float*)d_in[4];
    const float* att_em_i = (const float*)d_in[5];
    const float* att_em_j = (const float*)d_in[6];
    // d_in[7] = gnn_bias: cancels exactly inside BN1 (per-channel constant)
    const float* bn1_g    = (const float*)d_in[8];
    const float* bn1_b    = (const float*)d_in[9];
    const float* bn2_g    = (const float*)d_in[10];
    const float* bn2_b    = (const float*)d_in[11];
    const float* enc_w    = (const float*)d_in[12];
    const float* enc_b    = (const float*)d_in[13];
    const float* arr_w    = (const float*)d_in[14];
    const float* arr_b    = (const float*)d_in[15];
    const float* out_w    = (const float*)d_in[16];
    const float* out_b    = (const float*)d_in[17];
    float* out = (float*)d_out;

    const size_t smemB = (size_t)(NODE*XLS + 3*256 + 10496)*4;   // 114688 B
    cudaFuncSetAttribute(k_all, cudaFuncAttributeMaxDynamicSharedMemorySize, (int)smemB);

    k_all<<<256,512,smemB>>>(data, lin_w, emb, att_i, att_j, att_em_i, att_em_j,
                             bn1_g, bn1_b, bn2_g, bn2_b, enc_w, enc_b,
                             arr_w, arr_b, out_w, out_b, out);
}

// round 17
// speedup vs baseline: 1.2224x; 1.2224x over previous
#include <cuda_runtime.h>
#include <math.h>

#define BATCH 256
#define NODE  256
#define DIM   64
#define TOPK  20
#define XLS 68   // padded shared stride for xl rows (16B-aligned for float4)

// ---------------- scratch (device globals; no allocations) ----------------
__device__ int   g_topk[NODE*TOPK];
__device__ float g_xl [65536*DIM];
__device__ float g_agg[65536*DIM];
__device__ float g_p1s[64*256], g_p1q[64*256];     // BN1 partials [c][p]
__device__ float g_p2s[64*512], g_p2q[64*512];     // BN2 partials [c][p]
__device__ float g_mean1[DIM], g_rstd1[DIM];
__device__ float g_mean2[DIM], g_rstd2[DIM];
__device__ float g_W2[16384*7];          // enc_w @ arr_w
__device__ float g_arrP[16*BATCH*7];     // [kc][b][j] partials

__device__ __forceinline__ float lrelu(float x){ return x >= 0.f ? x : 0.2f*x; }

// ---------------- K1: cosine topk (blocks 0..255) + W2 precompute (blocks 256..319) ----------------
__global__ void k_pre(const float* __restrict__ emb,
                      const float* __restrict__ enc_w, const float* __restrict__ arr_w){
    __shared__ float nrm[NODE];
    __shared__ float vals[NODE];
    __shared__ float wv[8];
    __shared__ int   wi[8];
    __shared__ int   winner;
    __shared__ float aws[64*7];
    int tid = threadIdx.x;

    if (blockIdx.x >= 256){
        // ---- W2 = enc_w @ arr_w : one thread per k-row ----
        int blk = blockIdx.x - 256;
        for (int idx = tid; idx < 448; idx += 256) aws[idx] = arr_w[idx];
        __syncthreads();
        int k = blk*256 + tid;
        const float4* er = (const float4*)&enc_w[(size_t)k*64];
        float acc[7] = {};
#pragma unroll
        for (int m=0;m<16;m++){
            float4 q = er[m];
            int c = m*4;
#pragma unroll
            for (int j=0;j<7;j++){
                acc[j] += q.x*aws[(c  )*7+j] + q.y*aws[(c+1)*7+j]
                        + q.z*aws[(c+2)*7+j] + q.w*aws[(c+3)*7+j];
            }
        }
#pragma unroll
        for (int j=0;j<7;j++) g_W2[(size_t)k*7+j] = acc[j];
        return;
    }

    // ---- cosine top-k for node i = blockIdx.x ----
    int i = blockIdx.x;
    int j = tid;
    int lane = j & 31, warp = j >> 5;
    const float* wj = emb + j*DIM;
    float s = 0.f;
#pragma unroll
    for (int k=0;k<DIM;k++){ float v = wj[k]; s += v*v; }
    nrm[j] = sqrtf(s);
    __syncthreads();
    const float* wi_row = emb + i*DIM;
    float d = 0.f;
#pragma unroll
    for (int k=0;k<DIM;k++) d += wi_row[k]*wj[k];
    vals[j] = d / (nrm[i]*nrm[j]);
    __syncthreads();
    for (int t=0;t<TOPK;t++){
        float v = vals[j]; int idx = j;
#pragma unroll
        for (int off=16; off; off>>=1){
            float v2 = __shfl_xor_sync(0xffffffffu, v, off);
            int   i2 = __shfl_xor_sync(0xffffffffu, idx, off);
            if (v2 > v || (v2 == v && i2 < idx)){ v = v2; idx = i2; }
        }
        if (lane == 0){ wv[warp] = v; wi[warp] = idx; }
        __syncthreads();
        if (j < 8){
            float v8 = wv[j]; int i8 = wi[j];
#pragma unroll
            for (int off=4; off; off>>=1){
                float v2 = __shfl_xor_sync(0xffu, v8, off);
                int   i2 = __shfl_xor_sync(0xffu, i8, off);
                if (v2 > v8 || (v2 == v8 && i2 < i8)){ v8 = v2; i8 = i2; }
            }
            if (j == 0){ g_topk[i*TOPK + t] = i8; winner = i8; }
        }
        __syncthreads();
        if (j == winner) vals[j] = -3e38f;
        __syncthreads();
    }
}

// ---------------- K2: xl = data @ lin_w  (64 rows / block, 4x4 register tiles) ----------------
__global__ __launch_bounds__(256) void k_lin(const float* __restrict__ x, const float* __restrict__ lw){
    __shared__ float xs[64][65];
    __shared__ float ws[64][65];
    int r0 = blockIdx.x*64;
    int tid = threadIdx.x;
#pragma unroll
    for (int it=0; it<16; it++){
        int idx = tid + it*256;
        int r = idx>>6, c = idx&63;
        xs[r][c] = x[(size_t)(r0+r)*64 + c];
        ws[r][c] = lw[idx];
    }
    __syncthreads();
    int tr = tid>>4, tc = tid&15;
    float acc[4][4] = {};
#pragma unroll 8
    for (int k=0;k<64;k++){
        float a[4], b[4];
#pragma unroll
        for (int u=0;u<4;u++){ a[u]=xs[tr*4+u][k]; b[u]=ws[k][tc*4+u]; }
#pragma unroll
        for (int u=0;u<4;u++)
#pragma unroll
            for (int v=0;v<4;v++) acc[u][v] += a[u]*b[v];
    }
#pragma unroll
    for (int u=0;u<4;u++)
#pragma unroll
        for (int v=0;v<4;v++)
            g_xl[(size_t)(r0+tr*4+u)*64 + tc*4+v] = acc[u][v];
}

// ---------------- K3: per-batch GAT aggregation + BN1 partial stats (xl from gmem) ----------------
__global__ __launch_bounds__(512,2) void k_agg(
        const float* __restrict__ emb,
        const float* __restrict__ att_i, const float* __restrict__ att_j,
        const float* __restrict__ att_em_i, const float* __restrict__ att_em_j){
    extern __shared__ float sm[];
    float* xls  = sm;                     // 256*68 = 17408
    float* si   = xls + NODE*XLS;         // 256
    float* sj   = si + NODE;              // 256
    float* attv = sj + NODE;              // 256
    float* U    = attv + 256;             // 10496 floats union

    int b = blockIdx.x;
    int tid = threadIdx.x;

    // ---- stage xl[b] into shared (coalesced float4) ----
    {
        const float4* src = (const float4*)(g_xl + (size_t)b*NODE*DIM);
#pragma unroll
        for (int it=0; it<8; it++){
            int idx4 = tid + it*512;          // 0..4095
            int row = idx4 >> 4;
            int c4  = (idx4 & 15) * 4;
            *(float4*)&xls[row*XLS + c4] = src[idx4];
        }
    }
    if (tid < 64)       attv[tid] = att_i[tid];
    else if (tid < 128) attv[tid] = att_j[tid-64];
    else if (tid < 192) attv[tid] = att_em_i[tid-128];
    else if (tid < 256) attv[tid] = att_em_j[tid-192];

    // ---- phase B: topk, per-node scalars, softmax ----
    int*   tk  = (int*)U;          // 5120 ints
    float* alp = U + 5120;         // 5376 floats
    for (int idx=tid; idx<NODE*TOPK; idx+=512) tk[idx] = g_topk[idx];
    __syncthreads();
    if (tid < 256){
        int i = tid;
        float ai = 0.f, aj = 0.f;
#pragma unroll
        for (int d=0; d<DIM; d++){
            float x = xls[i*XLS + d];
            float e = emb[i*DIM + d];
            ai += x*attv[d]    + e*attv[128+d];
            aj += x*attv[64+d] + e*attv[192+d];
        }
        si[i] = ai; sj[i] = aj;
    }
    __syncthreads();
    if (tid < 256){
        int i = tid;
        float svi = si[i];
        int   sidx[TOPK];
        float lv[TOPK];
#pragma unroll
        for (int k=0;k<TOPK;k++) sidx[k] = tk[i*TOPK+k];
#pragma unroll
        for (int k=0;k<TOPK;k++) lv[k] = lrelu(svi + sj[sidx[k]]);
        float lself = lrelu(svi + sj[i]);
        float m = lself;
#pragma unroll
        for (int k=0;k<TOPK;k++) if (sidx[k] != i) m = fmaxf(m, lv[k]);
        float sum = 0.f;
#pragma unroll
        for (int k=0;k<TOPK;k++){
            float a = (sidx[k] != i) ? expf(lv[k] - m) : 0.f;
            alp[i*21+k] = a; sum += a;
        }
        float as = expf(lself - m);
        alp[i*21+20] = as; sum += as;
        float inv = 1.f/sum;
#pragma unroll
        for (int k=0;k<21;k++) alp[i*21+k] *= inv;
    }
    __syncthreads();

    // ---- phase C: weighted aggregation (float4 lanes, 2 nodes/pass) + stats ----
    int w = tid>>5, l = tid&31;
    int half = l>>4;            // 0: even-node, 1: odd-node
    int lc = l&15;
    int c0 = 4*lc;
    float sA0=0.f,sA1=0.f,sA2=0.f,sA3=0.f;
    float sQ0=0.f,sQ1=0.f,sQ2=0.f,sQ3=0.f;
#pragma unroll 2
    for (int p=0; p<8; p++){
        int i = w*16 + 2*p + half;
        float ax=0.f, ay=0.f, az=0.f, aw=0.f;
        int base = i*21;
#pragma unroll
        for (int k=0;k<21;k++){
            float a = alp[base+k];
            int s = (k<TOPK) ? tk[i*TOPK+k] : i;
            float4 v = *(const float4*)&xls[s*XLS + c0];
            ax += a*v.x; ay += a*v.y; az += a*v.z; aw += a*v.w;
        }
        int g = b*NODE + i;
        float4 o; o.x=ax; o.y=ay; o.z=az; o.w=aw;
        *(float4*)&g_agg[(size_t)g*DIM + c0] = o;
        sA0+=ax; sQ0+=ax*ax; sA1+=ay; sQ1+=ay*ay;
        sA2+=az; sQ2+=az*az; sA3+=aw; sQ3+=aw*aw;
    }
    // merge half-warps (same channels)
    sA0 += __shfl_down_sync(0xffffffffu, sA0, 16);
    sA1 += __shfl_down_sync(0xffffffffu, sA1, 16);
    sA2 += __shfl_down_sync(0xffffffffu, sA2, 16);
    sA3 += __shfl_down_sync(0xffffffffu, sA3, 16);
    sQ0 += __shfl_down_sync(0xffffffffu, sQ0, 16);
    sQ1 += __shfl_down_sync(0xffffffffu, sQ1, 16);
    sQ2 += __shfl_down_sync(0xffffffffu, sQ2, 16);
    sQ3 += __shfl_down_sync(0xffffffffu, sQ3, 16);
    __syncthreads();
    float* ssum = U;            // 16*64
    float* ssq  = U + 1024;     // 16*64
    if (l < 16){
        ssum[w*64 + c0  ] = sA0; ssq[w*64 + c0  ] = sQ0;
        ssum[w*64 + c0+1] = sA1; ssq[w*64 + c0+1] = sQ1;
        ssum[w*64 + c0+2] = sA2; ssq[w*64 + c0+2] = sQ2;
        ssum[w*64 + c0+3] = sA3; ssq[w*64 + c0+3] = sQ3;
    }
    __syncthreads();
    if (tid < 64){
        float s=0.f, q=0.f;
#pragma unroll
        for (int ww=0; ww<16; ww++){ s += ssum[ww*64 + tid]; q += ssq[ww*64 + tid]; }
        g_p1s[tid*256 + b] = s;
        g_p1q[tid*256 + b] = q;
    }
}

// ---------------- K4: finalize BN stats (block per channel) + optional arrfin role ----------------
__global__ void k_fin(int which, const float* __restrict__ enc_b,
                      const float* __restrict__ arr_w, const float* __restrict__ arr_b,
                      float* __restrict__ out){
    int bx = blockIdx.x;
    int tid = threadIdx.x;
    if (bx >= 64){
        int gid = (bx-64)*256 + tid;
        if (gid < BATCH*7){
            int b = gid / 7, j = gid - b*7;
            float s = 0.f;
#pragma unroll
            for (int kc=0;kc<16;kc++) s += g_arrP[(kc*256 + b)*7 + j];
            float bias = arr_b[j];
#pragma unroll
            for (int c=0;c<64;c++) bias += enc_b[c]*arr_w[c*7+j];
            out[65536 + gid] = s + bias;
        }
        return;
    }
    __shared__ float sh[256], shq[256];
    int c = bx;
    float s, q;
    if (which){
        s = g_p2s[c*512 + tid] + g_p2s[c*512 + 256 + tid];
        q = g_p2q[c*512 + tid] + g_p2q[c*512 + 256 + tid];
    } else {
        s = g_p1s[c*256 + tid];
        q = g_p1q[c*256 + tid];
    }
    sh[tid]=s; shq[tid]=q;
    __syncthreads();
#pragma unroll
    for (int off=128; off>32; off>>=1){
        if (tid < off){ sh[tid]+=sh[tid+off]; shq[tid]+=shq[tid+off]; }
        __syncthreads();
    }
    if (tid < 32){
        float a = sh[tid]+sh[tid+32];
        float b2 = shq[tid]+shq[tid+32];
#pragma unroll
        for (int off=16; off; off>>=1){
            a  += __shfl_down_sync(0xffffffffu, a, off);
            b2 += __shfl_down_sync(0xffffffffu, b2, off);
        }
        if (tid == 0){
            double m = (double)a/65536.0;
            double var = (double)b2/65536.0 - m*m;
            if (which){ g_mean2[c]=(float)m; g_rstd2[c]=1.0f/sqrtf((float)var + 1e-5f); }
            else      { g_mean1[c]=(float)m; g_rstd1[c]=1.0f/sqrtf((float)var + 1e-5f); }
        }
    }
}

// ---------------- K5: arrangement partials via W2 (direct L2) + BN1 inline + BN2 partial stats ----------------
__global__ __launch_bounds__(256) void k_encarr(
        const float* __restrict__ emb,
        const float* __restrict__ g1, const float* __restrict__ b1){
    __shared__ float ssum[8][64];
    __shared__ float ssq[8][64];
    int tid = threadIdx.x;
    int w = tid>>5, l = tid&31;
    int kc = blockIdx.y;
    int kbase = kc*1024;
    int b = blockIdx.x*8 + w;
    int c0 = 4*(l&15);
    int npar = l>>4;

    float4 mn = *(const float4*)&g_mean1[c0];
    float4 rs = *(const float4*)&g_rstd1[c0];
    float4 ga = *(const float4*)&g1[c0];
    float4 be = *(const float4*)&b1[c0];

    const float* arow = g_agg + (size_t)b*16384 + kbase;
    float acc[7] = {};
    float sA0=0.f,sA1=0.f,sA2=0.f,sA3=0.f;
    float sQ0=0.f,sQ1=0.f,sQ2=0.f,sQ3=0.f;
#pragma unroll
    for (int t=0; t<8; t++){
        int kl = t*128 + l*4;
        float4 v = __ldcs((const float4*)&arow[kl]);
        int n = kc*16 + t*2 + npar;
        float4 e = *(const float4*)&emb[n*64 + c0];
        float gn0 = fmaxf(0.f, (v.x-mn.x)*rs.x*ga.x + be.x);
        float gn1 = fmaxf(0.f, (v.y-mn.y)*rs.y*ga.y + be.y);
        float gn2 = fmaxf(0.f, (v.z-mn.z)*rs.z*ga.z + be.z);
        float gn3 = fmaxf(0.f, (v.w-mn.w)*rs.w*ga.w + be.w);
        float y0 = gn0*e.x, y1 = gn1*e.y, y2 = gn2*e.z, y3 = gn3*e.w;
        sA0+=y0; sQ0+=y0*y0; sA1+=y1; sQ1+=y1*y1;
        sA2+=y2; sQ2+=y2*y2; sA3+=y3; sQ3+=y3*y3;
        const float4* wp = (const float4*)&g_W2[(size_t)(kbase+kl)*7];
        float wf[28];
#pragma unroll
        for (int m=0;m<7;m++){
            float4 q = __ldg(&wp[m]);
            wf[4*m]=q.x; wf[4*m+1]=q.y; wf[4*m+2]=q.z; wf[4*m+3]=q.w;
        }
        float gn[4] = {gn0,gn1,gn2,gn3};
#pragma unroll
        for (int i=0;i<4;i++)
#pragma unroll
            for (int j=0;j<7;j++) acc[j] += gn[i]*wf[i*7+j];
    }
    // arrangement partial: reduce across full warp (covers the whole 1024-k chunk)
#pragma unroll
    for (int j=0;j<7;j++){
#pragma unroll
        for (int off=16; off; off>>=1)
            acc[j] += __shfl_xor_sync(0xffffffffu, acc[j], off);
    }
    if (l == 0){
#pragma unroll
        for (int j=0;j<7;j++) g_arrP[(kc*256 + b)*7 + j] = acc[j];
    }
    // BN2 stats: lanes l and l+16 share channels c0..c0+3
    sA0 += __shfl_down_sync(0xffffffffu, sA0, 16);
    sA1 += __shfl_down_sync(0xffffffffu, sA1, 16);
    sA2 += __shfl_down_sync(0xffffffffu, sA2, 16);
    sA3 += __shfl_down_sync(0xffffffffu, sA3, 16);
    sQ0 += __shfl_down_sync(0xffffffffu, sQ0, 16);
    sQ1 += __shfl_down_sync(0xffffffffu, sQ1, 16);
    sQ2 += __shfl_down_sync(0xffffffffu, sQ2, 16);
    sQ3 += __shfl_down_sync(0xffffffffu, sQ3, 16);
    if (l < 16){
        ssum[w][c0  ] = sA0; ssq[w][c0  ] = sQ0;
        ssum[w][c0+1] = sA1; ssq[w][c0+1] = sQ1;
        ssum[w][c0+2] = sA2; ssq[w][c0+2] = sQ2;
        ssum[w][c0+3] = sA3; ssq[w][c0+3] = sQ3;
    }
    __syncthreads();
    if (tid < 64){
        float s=0.f, q=0.f;
#pragma unroll
        for (int ww=0; ww<8; ww++){ s += ssum[ww][tid]; q += ssq[ww][tid]; }
        int pid = blockIdx.y*32 + blockIdx.x;
        g_p2s[tid*512 + pid] = s;
        g_p2q[tid*512 + pid] = q;
    }
}

// ---------------- K6: score head (BN1 inline + mul emb + BN2 + relu + dot) ----------------
__global__ void k_score(const float* __restrict__ emb,
                        const float* __restrict__ g1, const float* __restrict__ b1,
                        const float* __restrict__ g2, const float* __restrict__ b2,
                        const float* __restrict__ out_w, const float* __restrict__ out_b,
                        float* __restrict__ out){
    int w = threadIdx.x>>5, l = threadIdx.x&31;
    int g = blockIdx.x*8 + w;
    int n = g & 255;
    int d = 2*l;
    float2 v = __ldcs((const float2*)&g_agg[(size_t)g*DIM + d]);
    float2 e = *(const float2*)&emb[n*DIM + d];
    float gn0 = fmaxf(0.f, (v.x - g_mean1[d  ])*g_rstd1[d  ]*g1[d  ] + b1[d  ]);
    float gn1 = fmaxf(0.f, (v.y - g_mean1[d+1])*g_rstd1[d+1]*g1[d+1] + b1[d+1]);
    float y0 = gn0*e.x, y1 = gn1*e.y;
    float r0 = fmaxf(0.f, (y0 - g_mean2[d  ])*g_rstd2[d  ]*g2[d  ] + b2[d  ]);
    float r1 = fmaxf(0.f, (y1 - g_mean2[d+1])*g_rstd2[d+1]*g2[d+1] + b2[d+1]);
    float p = r0*out_w[d] + r1*out_w[d+1];
#pragma unroll
    for (int off=16; off; off>>=1) p += __shfl_down_sync(0xffffffffu, p, off);
    if (l == 0) out[g] = p + out_b[0];
}

// ---------------- launcher ----------------
extern "C" void kernel_launch(void* const* d_in, const int* in_sizes, int n_in,
                              void* d_out, int out_size){
    const float* data     = (const float*)d_in[0];
    const float* emb      = (const float*)d_in[1];
    const float* lin_w    = (const float*)d_in[2];
    const float* att_i    = (const float*)d_in[3];
    const float* att_j    = (const float*)d_in[4];
    const float* att_em_i = (const float*)d_in[5];
    const float* att_em_j = (const float*)d_in[6];
    // d_in[7] = gnn_bias: cancels exactly inside BN1 (per-channel constant)
    const float* bn1_g    = (const float*)d_in[8];
    const float* bn1_b    = (const float*)d_in[9];
    const float* bn2_g    = (const float*)d_in[10];
    const float* bn2_b    = (const float*)d_in[11];
    const float* enc_w    = (const float*)d_in[12];
    const float* enc_b    = (const float*)d_in[13];
    const float* arr_w    = (const float*)d_in[14];
    const float* arr_b    = (const float*)d_in[15];
    const float* out_w    = (const float*)d_in[16];
    const float* out_b    = (const float*)d_in[17];
    float* out = (float*)d_out;

    const size_t aggSmem = (size_t)(NODE*XLS + 3*256 + 10496)*4;   // 114688 B
    cudaFuncSetAttribute(k_agg, cudaFuncAttributeMaxDynamicSharedMemorySize, (int)aggSmem);

    k_pre<<<320,256>>>(emb, enc_w, arr_w);
    k_lin<<<1024,256>>>(data, lin_w);
    k_agg<<<256,512,aggSmem>>>(emb, att_i, att_j, att_em_i, att_em_j);
    k_fin<<<64,256>>>(0, enc_b, arr_w, arr_b, out);
    k_encarr<<<dim3(32,16),256>>>(emb, bn1_g, bn1_b);
    k_fin<<<72,256>>>(1, enc_b, arr_w, arr_b, out);
    k_score<<<8192,256>>>(emb, bn1_g, bn1_b, bn2_g, bn2_b, out_w, out_b, out);
}